// round 2
// baseline (speedup 1.0000x reference)
#include <cuda_runtime.h>

// ---------------------------------------------------------------------------
// Problem constants
// ---------------------------------------------------------------------------
#define Bn      1024
#define Tt      34
#define E       128
#define TWO_E   256
#define L0N     (Bn*Tt*8)    // 278528
#define L1N     (Bn*Tt*4)    // 139264
#define L2N     (Bn*Tt*2)    // 69632
#define L3N     (Bn*Tt)      // 34816
#define LFN     (Bn*9)       // 9216
#define LBASE0  0
#define LBASE1  (LBASE0 + 4*L0N)
#define LBASE2  (LBASE1 + 4*L1N)
#define LBASE3  (LBASE2 + 4*L2N)
#define LBASE4  (LBASE3 + 4*L3N)
#define LTOTAL  (LBASE4 + 3*LFN)
#define TM      32
// smem layouts (Ps aliases Xs: Xs dead after GEMM1)
#define NF_SMEM (32768 + 32768 + 128)
#define LF_SMEM (32768 + 65536 + 128)

// ---------------------------------------------------------------------------
// Scratch (device globals; no allocation allowed)
// ---------------------------------------------------------------------------
__device__ float g_buf0[(size_t)L0N * E];   // level0 out / level2 out
__device__ float g_buf1[(size_t)L1N * E];   // level1 out
__device__ float g_roots[(size_t)L3N * E];  // level3 out (B,34,128)
__device__ float g_stmt[(size_t)LFN * E];   // lf out (B,9,128)
__device__ int   g_counts[20];              // 4 levels x 4 experts + lf x 3
__device__ int   g_lists[LTOTAL];

// ---------------------------------------------------------------------------
// Zero the per-expert counters (graph replays must reset state)
// ---------------------------------------------------------------------------
__global__ void zero_counts_kernel() {
    if (threadIdx.x < 20) g_counts[threadIdx.x] = 0;
}

// ---------------------------------------------------------------------------
// Expert compaction: every node (all 4 tree levels + lf stage) appends its
// linear node id into its expert's list. Warp-aggregated atomics.
// Grid is an exact multiple of 256 (531456 = 2076*256): full warps.
// ---------------------------------------------------------------------------
__global__ void compact_kernel(const int* __restrict__ nf_ids,
                               const int* __restrict__ lf_ids) {
    int gid = blockIdx.x * 256 + threadIdx.x;
    int slot, store_base, nid;
    if (gid < L0N) {
        nid = gid;
        int bt = nid >> 3, j = nid & 7;
        int id = nf_ids[bt * 15 + j];
        slot = id;               store_base = LBASE0 + id * L0N;
    } else if (gid < L0N + L1N) {
        nid = gid - L0N;
        int bt = nid >> 2, j = nid & 3;
        int id = nf_ids[bt * 15 + 8 + j];
        slot = 4 + id;           store_base = LBASE1 + id * L1N;
    } else if (gid < L0N + L1N + L2N) {
        nid = gid - (L0N + L1N);
        int bt = nid >> 1, j = nid & 1;
        int id = nf_ids[bt * 15 + 12 + j];
        slot = 8 + id;           store_base = LBASE2 + id * L2N;
    } else if (gid < L0N + L1N + L2N + L3N) {
        nid = gid - (L0N + L1N + L2N);
        int id = nf_ids[nid * 15 + 14];
        slot = 12 + id;          store_base = LBASE3 + id * L3N;
    } else {
        nid = gid - (L0N + L1N + L2N + L3N);
        int id = lf_ids[nid];
        slot = 16 + id;          store_base = LBASE4 + id * LFN;
    }
    unsigned mm = __match_any_sync(0xFFFFFFFFu, slot);
    int lane   = threadIdx.x & 31;
    int leader = __ffs(mm) - 1;
    int rank   = __popc(mm & ((1u << lane) - 1));
    int base   = 0;
    if (lane == leader) base = atomicAdd(&g_counts[slot], __popc(mm));
    base = __shfl_sync(0xFFFFFFFFu, base, leader);
    g_lists[store_base + base + rank] = nid;
}

// ---------------------------------------------------------------------------
// Tree-level expert MLP: out = relu(x @ W1 + b1) @ W2 + b2
//   x: 256, hidden: 256, out: 128. One block = 32 nodes of one expert.
//   GEMM1: thread j owns hidden col j, 32 row-accumulators, x broadcast via
//   float4 smem reads. GEMM2: split-K across two thread halves + smem reduce.
// ---------------------------------------------------------------------------
__global__ void __launch_bounds__(256, 2)
nf_gemm_kernel(int lvl,
               const int* __restrict__ leaf_idx,
               const float* __restrict__ ent_emb,
               const float* __restrict__ W1, const float* __restrict__ b1,
               const float* __restrict__ W2, const float* __restrict__ b2) {
    extern __shared__ char smem[];
    float4* Xs = (float4*)smem;               // [32][64]  32KB
    float4* Hs = (float4*)(smem + 32768);     // [32][64]  32KB
    float*  Ps = (float*)smem;                // aliases Xs after GEMM1
    int* s_node = (int*)(smem + 65536);

    int stride, list_base, counts_off;
    const float* in; float* outp;
    switch (lvl) {
        case 0:  stride = L0N; list_base = LBASE0; counts_off = 0;  in = 0;      outp = g_buf0;  break;
        case 1:  stride = L1N; list_base = LBASE1; counts_off = 4;  in = g_buf0; outp = g_buf1;  break;
        case 2:  stride = L2N; list_base = LBASE2; counts_off = 8;  in = g_buf1; outp = g_buf0;  break;
        default: stride = L3N; list_base = LBASE3; counts_off = 12; in = g_buf0; outp = g_roots; break;
    }

    int k_ex  = blockIdx.y;
    int count = g_counts[counts_off + k_ex];
    int m0    = blockIdx.x * TM;
    if (m0 >= count) return;
    int mrows = min(TM, count - m0);
    int tid   = threadIdx.x;

    if (tid < TM)
        s_node[tid] = (tid < mrows) ? g_lists[list_base + k_ex * stride + m0 + tid] : -1;
    __syncthreads();

    // ---- stage X tile: 8 threads per row, 8 float4 each --------------------
    {
        int m = tid >> 3, p = tid & 7;
        int node = s_node[m];
        if (node >= 0) {
            if (lvl == 0) {
                int half = p >> 2;                         // 0: left leaf, 1: right leaf
                int l = leaf_idx[node * 2 + half];
                const float4* src = (const float4*)(ent_emb + (size_t)l * E);
                int f4l = (p & 3) * 8;
                #pragma unroll
                for (int q = 0; q < 8; q++)
                    Xs[m * 64 + p * 8 + q] = src[f4l + q];
            } else {
                const float4* src = (const float4*)(in + (size_t)node * TWO_E);
                #pragma unroll
                for (int q = 0; q < 8; q++)
                    Xs[m * 64 + p * 8 + q] = src[p * 8 + q];
            }
        }
    }
    __syncthreads();

    // ---- GEMM1: h[m][tid] = sum_k x[m][k] * W1[k][tid] ---------------------
    const float* W1k = W1 + (size_t)k_ex * TWO_E * TWO_E;
    float acc[TM];
    #pragma unroll
    for (int m = 0; m < TM; m++) acc[m] = 0.f;
    #pragma unroll 2
    for (int k = 0; k < TWO_E; k += 4) {
        const float* wp = W1k + k * TWO_E + tid;
        float w0 = __ldg(wp);
        float w1 = __ldg(wp + TWO_E);
        float w2 = __ldg(wp + 2 * TWO_E);
        float w3 = __ldg(wp + 3 * TWO_E);
        int kq = k >> 2;
        #pragma unroll
        for (int m = 0; m < TM; m++) {
            float4 x = Xs[m * 64 + kq];
            acc[m] = fmaf(x.x, w0, acc[m]);
            acc[m] = fmaf(x.y, w1, acc[m]);
            acc[m] = fmaf(x.z, w2, acc[m]);
            acc[m] = fmaf(x.w, w3, acc[m]);
        }
    }
    {
        float bias1 = b1[k_ex * TWO_E + tid];
        float* Hf = (float*)Hs;
        #pragma unroll
        for (int m = 0; m < TM; m++) {
            float h = acc[m] + bias1;
            Hf[m * TWO_E + tid] = h > 0.f ? h : 0.f;
        }
    }
    __syncthreads();   // Hs valid; Xs dead -> Ps may alias

    // ---- GEMM2: out[m][j2] = sum_j h[m][j] * W2[j][j2] (split-K halves) ----
    const float* W2k = W2 + (size_t)k_ex * TWO_E * E;
    int j2 = tid & (E - 1);
    int half = tid >> 7;
    #pragma unroll
    for (int m = 0; m < TM; m++) acc[m] = 0.f;
    int kb = half * 128;
    #pragma unroll 2
    for (int k = 0; k < 128; k += 4) {
        int kk = kb + k;
        const float* wp = W2k + kk * E + j2;
        float w0 = __ldg(wp);
        float w1 = __ldg(wp + E);
        float w2 = __ldg(wp + 2 * E);
        float w3 = __ldg(wp + 3 * E);
        int kq = kk >> 2;
        #pragma unroll
        for (int m = 0; m < TM; m++) {
            float4 h = Hs[m * 64 + kq];
            acc[m] = fmaf(h.x, w0, acc[m]);
            acc[m] = fmaf(h.y, w1, acc[m]);
            acc[m] = fmaf(h.z, w2, acc[m]);
            acc[m] = fmaf(h.w, w3, acc[m]);
        }
    }
    if (half) {
        #pragma unroll
        for (int m = 0; m < TM; m++) Ps[m * E + j2] = acc[m];
    }
    __syncthreads();
    if (!half) {
        float bias2 = b2[k_ex * E + j2];
        for (int m = 0; m < mrows; m++) {
            int node = s_node[m];
            outp[(size_t)node * E + j2] = acc[m] + Ps[m * E + j2] + bias2;
        }
    }
}

// ---------------------------------------------------------------------------
// Leaf/statement expert MLP: 256 -> 512 relu -> 128 on pairs from roots.
// ---------------------------------------------------------------------------
__global__ void __launch_bounds__(256, 2)
lf_gemm_kernel(const float* __restrict__ W1, const float* __restrict__ b1,
               const float* __restrict__ W2, const float* __restrict__ b2) {
    extern __shared__ char smem[];
    float4* Xs = (float4*)smem;               // [32][64]   32KB
    float4* Hs = (float4*)(smem + 32768);     // [32][128]  64KB
    float*  Ps = (float*)smem;                // aliases Xs after GEMM1
    int* s_node = (int*)(smem + 98304);

    int k_ex  = blockIdx.y;
    int count = g_counts[16 + k_ex];
    int m0    = blockIdx.x * TM;
    if (m0 >= count) return;
    int mrows = min(TM, count - m0);
    int tid   = threadIdx.x;

    if (tid < TM)
        s_node[tid] = (tid < mrows) ? g_lists[LBASE4 + k_ex * LFN + m0 + tid] : -1;
    __syncthreads();

    {
        int m = tid >> 3, p = tid & 7;
        int node = s_node[m];
        if (node >= 0) {
            int b = node / 9, g = node % 9;
            const float4* src = (const float4*)(g_roots + ((size_t)b * Tt + 16 + 2 * g) * E);
            #pragma unroll
            for (int q = 0; q < 8; q++)
                Xs[m * 64 + p * 8 + q] = src[p * 8 + q];
        }
    }
    __syncthreads();

    // ---- GEMM1 (hidden 512): two passes, thread covers cols tid and tid+256
    const float* W1k = W1 + (size_t)k_ex * TWO_E * 512;
    for (int pass = 0; pass < 2; pass++) {
        int col = tid + pass * 256;
        float acc[TM];
        #pragma unroll
        for (int m = 0; m < TM; m++) acc[m] = 0.f;
        #pragma unroll 2
        for (int k = 0; k < TWO_E; k += 4) {
            const float* wp = W1k + k * 512 + col;
            float w0 = __ldg(wp);
            float w1 = __ldg(wp + 512);
            float w2 = __ldg(wp + 1024);
            float w3 = __ldg(wp + 1536);
            int kq = k >> 2;
            #pragma unroll
            for (int m = 0; m < TM; m++) {
                float4 x = Xs[m * 64 + kq];
                acc[m] = fmaf(x.x, w0, acc[m]);
                acc[m] = fmaf(x.y, w1, acc[m]);
                acc[m] = fmaf(x.z, w2, acc[m]);
                acc[m] = fmaf(x.w, w3, acc[m]);
            }
        }
        float bias1 = b1[k_ex * 512 + col];
        float* Hf = (float*)Hs;
        #pragma unroll
        for (int m = 0; m < TM; m++) {
            float h = acc[m] + bias1;
            Hf[m * 512 + col] = h > 0.f ? h : 0.f;
        }
    }
    __syncthreads();

    // ---- GEMM2 (K=512): split-K halves of 256 each -------------------------
    const float* W2k = W2 + (size_t)k_ex * 512 * E;
    int j2 = tid & (E - 1);
    int half = tid >> 7;
    float acc[TM];
    #pragma unroll
    for (int m = 0; m < TM; m++) acc[m] = 0.f;
    int kb = half * 256;
    #pragma unroll 2
    for (int k = 0; k < 256; k += 4) {
        int kk = kb + k;
        const float* wp = W2k + kk * E + j2;
        float w0 = __ldg(wp);
        float w1 = __ldg(wp + E);
        float w2 = __ldg(wp + 2 * E);
        float w3 = __ldg(wp + 3 * E);
        int kq = kk >> 2;
        #pragma unroll
        for (int m = 0; m < TM; m++) {
            float4 h = Hs[m * 128 + kq];
            acc[m] = fmaf(h.x, w0, acc[m]);
            acc[m] = fmaf(h.y, w1, acc[m]);
            acc[m] = fmaf(h.z, w2, acc[m]);
            acc[m] = fmaf(h.w, w3, acc[m]);
        }
    }
    if (half) {
        #pragma unroll
        for (int m = 0; m < TM; m++) Ps[m * E + j2] = acc[m];
    }
    __syncthreads();
    if (!half) {
        float bias2 = b2[k_ex * E + j2];
        for (int m = 0; m < mrows; m++) {
            int node = s_node[m];
            g_stmt[(size_t)node * E + j2] = acc[m] + Ps[m * E + j2] + bias2;
        }
    }
}

// ---------------------------------------------------------------------------
// Attention tail: q = obj@W+b, softmax over keys, weighted sum. One block/b.
// ---------------------------------------------------------------------------
__global__ void attn_kernel(const int* __restrict__ th_idx,
                            const float* __restrict__ th_emb,
                            const float* __restrict__ he_W, const float* __restrict__ he_b,
                            const float* __restrict__ hg_W, const float* __restrict__ hg_b,
                            const float* __restrict__ ht_W, const float* __restrict__ ht_b,
                            float* __restrict__ out) {
    __shared__ float obj[E];
    __shared__ float q[E];
    __shared__ float keys[16][E + 1];
    __shared__ float a[16];
    int b = blockIdx.x, tid = threadIdx.x;

    float o = g_stmt[((size_t)b * 9 + 8) * E + tid];
    obj[tid] = o;
    out[(size_t)b * 512 + tid] = o;
    __syncthreads();

    for (int t3 = 0; t3 < 3; t3++) {
        int n; const float *W, *bb;
        if (t3 == 0) {
            n = 8; W = hg_W; bb = hg_b;
            for (int i = 0; i < 8; i++)
                keys[i][tid] = g_stmt[((size_t)b * 9 + i) * E + tid];
        } else if (t3 == 1) {
            n = 16; W = he_W; bb = he_b;
            for (int i = 0; i < 16; i++)
                keys[i][tid] = g_roots[((size_t)b * Tt + i) * E + tid];
        } else {
            n = 8; W = ht_W; bb = ht_b;
            for (int i = 0; i < 8; i++)
                keys[i][tid] = th_emb[(size_t)th_idx[b * 8 + i] * E + tid];
        }
        float qv = bb[tid];
        for (int k = 0; k < E; k++) qv = fmaf(obj[k], W[k * E + tid], qv);
        q[tid] = qv;
        __syncthreads();
        if (tid < n) {
            float s = 0.f;
            for (int d = 0; d < E; d++) s = fmaf(keys[tid][d], q[d], s);
            a[tid] = s;
        }
        __syncthreads();
        if (tid == 0) {
            float mx = -1e30f;
            for (int i = 0; i < n; i++) mx = fmaxf(mx, a[i]);
            float sum = 0.f;
            for (int i = 0; i < n; i++) { float e = expf(a[i] - mx); a[i] = e; sum += e; }
            float inv = 1.f / sum;
            for (int i = 0; i < n; i++) a[i] *= inv;
        }
        __syncthreads();
        float c = 0.f;
        for (int i = 0; i < n; i++) c = fmaf(a[i], keys[i][tid], c);
        int off = (t3 == 0) ? 128 : (t3 == 1) ? 256 : 384;
        out[(size_t)b * 512 + off + tid] = c;
        __syncthreads();
    }
}

// ---------------------------------------------------------------------------
extern "C" void kernel_launch(void* const* d_in, const int* in_sizes, int n_in,
                              void* d_out, int out_size) {
    const int*   leaf_idx = (const int*)d_in[0];
    const int*   nf_ids   = (const int*)d_in[1];
    const int*   lf_ids   = (const int*)d_in[2];
    const int*   th_idx   = (const int*)d_in[3];
    const float* ent_emb  = (const float*)d_in[4];
    const float* th_emb   = (const float*)d_in[5];
    const float* nf_W1 = (const float*)d_in[6];
    const float* nf_b1 = (const float*)d_in[7];
    const float* nf_W2 = (const float*)d_in[8];
    const float* nf_b2 = (const float*)d_in[9];
    const float* lf_W1 = (const float*)d_in[10];
    const float* lf_b1 = (const float*)d_in[11];
    const float* lf_W2 = (const float*)d_in[12];
    const float* lf_b2 = (const float*)d_in[13];
    const float* he_W = (const float*)d_in[14];
    const float* he_b = (const float*)d_in[15];
    const float* hg_W = (const float*)d_in[16];
    const float* hg_b = (const float*)d_in[17];
    const float* ht_W = (const float*)d_in[18];
    const float* ht_b = (const float*)d_in[19];
    float* out = (float*)d_out;

    cudaFuncSetAttribute(nf_gemm_kernel, cudaFuncAttributeMaxDynamicSharedMemorySize, NF_SMEM);
    cudaFuncSetAttribute(lf_gemm_kernel, cudaFuncAttributeMaxDynamicSharedMemorySize, LF_SMEM);

    zero_counts_kernel<<<1, 32>>>();
    compact_kernel<<<(L0N + L1N + L2N + L3N + LFN) / 256, 256>>>(nf_ids, lf_ids);

    nf_gemm_kernel<<<dim3(L0N / TM, 4), 256, NF_SMEM>>>(0, leaf_idx, ent_emb,
        nf_W1, nf_b1, nf_W2, nf_b2);
    nf_gemm_kernel<<<dim3(L1N / TM, 4), 256, NF_SMEM>>>(1, leaf_idx, ent_emb,
        nf_W1, nf_b1, nf_W2, nf_b2);
    nf_gemm_kernel<<<dim3(L2N / TM, 4), 256, NF_SMEM>>>(2, leaf_idx, ent_emb,
        nf_W1, nf_b1, nf_W2, nf_b2);
    nf_gemm_kernel<<<dim3(L3N / TM, 4), 256, NF_SMEM>>>(3, leaf_idx, ent_emb,
        nf_W1, nf_b1, nf_W2, nf_b2);

    lf_gemm_kernel<<<dim3(LFN / TM, 3), 256, LF_SMEM>>>(lf_W1, lf_b1, lf_W2, lf_b2);

    attn_kernel<<<Bn, E>>>(th_idx, th_emb, he_W, he_b, hg_W, hg_b, ht_W, ht_b, out);
}

// round 3
// speedup vs baseline: 4.3094x; 4.3094x over previous
#include <cuda_runtime.h>

// ---------------------------------------------------------------------------
// Problem constants
// ---------------------------------------------------------------------------
#define Bn      1024
#define Tt      34
#define E       128
#define TWO_E   256
#define L0N     (Bn*Tt*8)    // 278528
#define L1N     (Bn*Tt*4)    // 139264
#define L2N     (Bn*Tt*2)    // 69632
#define L3N     (Bn*Tt)      // 34816
#define LFN     (Bn*9)       // 9216
#define LBASE0  0
#define LBASE1  (LBASE0 + 4*L0N)
#define LBASE2  (LBASE1 + 4*L1N)
#define LBASE3  (LBASE2 + 4*L2N)
#define LBASE4  (LBASE3 + 4*L3N)
#define LTOTAL  (LBASE4 + 3*LFN)
#define TM      32
#define XSTR    36            // padded k-row stride for X_t / H_t (floats)

// smem layouts
//   nf: X_t 256*36*4=36864 | H_t 256*36*4=36864 | Ws 32768 | s_node 128
//   lf: X_t 36864          | H_t 512*36*4=73728 | Ws 32768 | s_node 128
#define NF_XT_OFF   0
#define NF_HT_OFF   36864
#define NF_WS_OFF   (36864 + 36864)
#define NF_SN_OFF   (NF_WS_OFF + 32768)
#define NF_SMEM     (NF_SN_OFF + 128)

#define LF_XT_OFF   0
#define LF_HT_OFF   36864
#define LF_WS_OFF   (36864 + 73728)
#define LF_SN_OFF   (LF_WS_OFF + 32768)
#define LF_SMEM     (LF_SN_OFF + 128)

// ---------------------------------------------------------------------------
// Scratch (device globals; no allocation allowed)
// ---------------------------------------------------------------------------
__device__ float g_buf0[(size_t)L0N * E];   // level0 out / level2 out
__device__ float g_buf1[(size_t)L1N * E];   // level1 out
__device__ float g_roots[(size_t)L3N * E];  // level3 out (B,34,128)
__device__ float g_stmt[(size_t)LFN * E];   // lf out (B,9,128)
__device__ int   g_counts[20];
__device__ int   g_lists[LTOTAL];

__global__ void zero_counts_kernel() {
    if (threadIdx.x < 20) g_counts[threadIdx.x] = 0;
}

// ---------------------------------------------------------------------------
// Expert compaction (warp-aggregated atomics). Grid exact multiple of 256.
// ---------------------------------------------------------------------------
__global__ void compact_kernel(const int* __restrict__ nf_ids,
                               const int* __restrict__ lf_ids) {
    int gid = blockIdx.x * 256 + threadIdx.x;
    int slot, store_base, nid;
    if (gid < L0N) {
        nid = gid;
        int bt = nid >> 3, j = nid & 7;
        int id = nf_ids[bt * 15 + j];
        slot = id;               store_base = LBASE0 + id * L0N;
    } else if (gid < L0N + L1N) {
        nid = gid - L0N;
        int bt = nid >> 2, j = nid & 3;
        int id = nf_ids[bt * 15 + 8 + j];
        slot = 4 + id;           store_base = LBASE1 + id * L1N;
    } else if (gid < L0N + L1N + L2N) {
        nid = gid - (L0N + L1N);
        int bt = nid >> 1, j = nid & 1;
        int id = nf_ids[bt * 15 + 12 + j];
        slot = 8 + id;           store_base = LBASE2 + id * L2N;
    } else if (gid < L0N + L1N + L2N + L3N) {
        nid = gid - (L0N + L1N + L2N);
        int id = nf_ids[nid * 15 + 14];
        slot = 12 + id;          store_base = LBASE3 + id * L3N;
    } else {
        nid = gid - (L0N + L1N + L2N + L3N);
        int id = lf_ids[nid];
        slot = 16 + id;          store_base = LBASE4 + id * LFN;
    }
    unsigned mm = __match_any_sync(0xFFFFFFFFu, slot);
    int lane   = threadIdx.x & 31;
    int leader = __ffs(mm) - 1;
    int rank   = __popc(mm & ((1u << lane) - 1));
    int base   = 0;
    if (lane == leader) base = atomicAdd(&g_counts[slot], __popc(mm));
    base = __shfl_sync(0xFFFFFFFFu, base, leader);
    g_lists[store_base + base + rank] = nid;
}

// ---------------------------------------------------------------------------
// nf expert MLP: 256 -> relu(256) -> 128.  Register-blocked SGEMM.
//   GEMM1: thread tile 4 rows x 8 cols (acc 32). X_t[k][m] transposed in smem,
//          W1 staged through smem in 32-k chunks with register prefetch.
//   GEMM2: thread tile 4 rows x 4 cols (acc 16), H_t[k][m] in smem.
// ---------------------------------------------------------------------------
__global__ void __launch_bounds__(256, 2)
nf_gemm_kernel(int lvl,
               const int* __restrict__ leaf_idx,
               const float* __restrict__ ent_emb,
               const float* __restrict__ W1, const float* __restrict__ b1,
               const float* __restrict__ W2, const float* __restrict__ b2) {
    extern __shared__ char smem[];
    float* Xt = (float*)(smem + NF_XT_OFF);       // [256][36]
    float* Ht = (float*)(smem + NF_HT_OFF);       // [256][36]
    float* Ws = (float*)(smem + NF_WS_OFF);       // [32][256] / [32][128]
    int* s_node = (int*)(smem + NF_SN_OFF);

    int stride, list_base, counts_off;
    const float* in; float* outp;
    switch (lvl) {
        case 0:  stride = L0N; list_base = LBASE0; counts_off = 0;  in = 0;      outp = g_buf0;  break;
        case 1:  stride = L1N; list_base = LBASE1; counts_off = 4;  in = g_buf0; outp = g_buf1;  break;
        case 2:  stride = L2N; list_base = LBASE2; counts_off = 8;  in = g_buf1; outp = g_buf0;  break;
        default: stride = L3N; list_base = LBASE3; counts_off = 12; in = g_buf0; outp = g_roots; break;
    }

    int k_ex  = blockIdx.y;
    int count = g_counts[counts_off + k_ex];
    int m0    = blockIdx.x * TM;
    if (m0 >= count) return;
    int mrows = min(TM, count - m0);
    int tid   = threadIdx.x;

    if (tid < TM)
        s_node[tid] = (tid < mrows) ? g_lists[list_base + k_ex * stride + m0 + tid] : -1;
    __syncthreads();

    // ---- stage X transposed: X_t[k][m]. Warp w handles rows 4w..4w+3; lane
    //      covers k = lane + 32j (coalesced gmem reads, conflict-light STS).
    {
        int wid = tid >> 5, lane = tid & 31;
        #pragma unroll
        for (int i = 0; i < 4; i++) {
            int m = wid * 4 + i;
            int node = s_node[m];
            if (lvl == 0) {
                int l0 = 0, l1 = 0;
                if (node >= 0) { l0 = leaf_idx[node * 2]; l1 = leaf_idx[node * 2 + 1]; }
                #pragma unroll
                for (int j = 0; j < 8; j++) {
                    int k = lane + 32 * j;
                    float v = 0.f;
                    if (node >= 0)
                        v = (k < E) ? ent_emb[(size_t)l0 * E + k]
                                    : ent_emb[(size_t)l1 * E + (k - E)];
                    Xt[k * XSTR + m] = v;
                }
            } else {
                const float* src = (node >= 0) ? (in + (size_t)node * TWO_E) : 0;
                #pragma unroll
                for (int j = 0; j < 8; j++) {
                    int k = lane + 32 * j;
                    Xt[k * XSTR + m] = src ? src[k] : 0.f;
                }
            }
        }
    }

    // ---- GEMM1: 32x256 = X(32x256) @ W1(256x256), k-chunks of 32 ----------
    int rg = tid & 7,  cg = tid >> 3;      // r0=4*rg, c0=8*cg
    int r0 = rg * 4,   c0 = cg * 8;
    const float* W1k = W1 + (size_t)k_ex * TWO_E * TWO_E;
    float acc[4][8];
    #pragma unroll
    for (int i = 0; i < 4; i++)
        #pragma unroll
        for (int j = 0; j < 8; j++) acc[i][j] = 0.f;

    float4 pre[8];
    {   // prefetch chunk 0 (tile is contiguous: rows 0..31 of 256-wide matrix)
        const float4* src = (const float4*)W1k;
        #pragma unroll
        for (int i = 0; i < 8; i++) pre[i] = __ldg(&src[tid + i * 256]);
    }
    for (int cb = 0; cb < 8; cb++) {
        float4* Wsv = (float4*)Ws;
        #pragma unroll
        for (int i = 0; i < 8; i++) Wsv[tid + i * 256] = pre[i];
        __syncthreads();
        if (cb < 7) {
            const float4* src = (const float4*)(W1k + (cb + 1) * 32 * TWO_E);
            #pragma unroll
            for (int i = 0; i < 8; i++) pre[i] = __ldg(&src[tid + i * 256]);
        }
        #pragma unroll
        for (int kk = 0; kk < 32; kk++) {
            float4 x  = *(const float4*)&Xt[(cb * 32 + kk) * XSTR + r0];
            float4 wa = *(const float4*)&Ws[kk * 256 + c0];
            float4 wb = *(const float4*)&Ws[kk * 256 + c0 + 4];
            float xs[4] = {x.x, x.y, x.z, x.w};
            float ws[8] = {wa.x, wa.y, wa.z, wa.w, wb.x, wb.y, wb.z, wb.w};
            #pragma unroll
            for (int i = 0; i < 4; i++)
                #pragma unroll
                for (int j = 0; j < 8; j++)
                    acc[i][j] = fmaf(xs[i], ws[j], acc[i][j]);
        }
        __syncthreads();
    }

    // ---- bias + relu -> H_t[c][m] (transposed for GEMM2) -------------------
    {
        float4 bva = __ldg((const float4*)(b1 + k_ex * TWO_E + c0));
        float4 bvb = __ldg((const float4*)(b1 + k_ex * TWO_E + c0 + 4));
        float bv[8] = {bva.x, bva.y, bva.z, bva.w, bvb.x, bvb.y, bvb.z, bvb.w};
        #pragma unroll
        for (int j = 0; j < 8; j++) {
            float4 h;
            h.x = fmaxf(acc[0][j] + bv[j], 0.f);
            h.y = fmaxf(acc[1][j] + bv[j], 0.f);
            h.z = fmaxf(acc[2][j] + bv[j], 0.f);
            h.w = fmaxf(acc[3][j] + bv[j], 0.f);
            *(float4*)&Ht[(c0 + j) * XSTR + r0] = h;
        }
    }
    __syncthreads();

    // ---- GEMM2: 32x128 = H(32x256) @ W2(256x128), k-chunks of 32 -----------
    int c2 = (tid >> 3) * 4;               // 32 col groups of 4
    float a2[4][4];
    #pragma unroll
    for (int i = 0; i < 4; i++)
        #pragma unroll
        for (int j = 0; j < 4; j++) a2[i][j] = 0.f;

    const float* W2k = W2 + (size_t)k_ex * TWO_E * E;
    float4 p2[4];
    {
        const float4* src = (const float4*)W2k;   // rows 0..31 contiguous
        #pragma unroll
        for (int i = 0; i < 4; i++) p2[i] = __ldg(&src[tid + i * 256]);
    }
    for (int cb = 0; cb < 8; cb++) {
        float4* Wsv = (float4*)Ws;
        #pragma unroll
        for (int i = 0; i < 4; i++) Wsv[tid + i * 256] = p2[i];
        __syncthreads();
        if (cb < 7) {
            const float4* src = (const float4*)(W2k + (cb + 1) * 32 * E);
            #pragma unroll
            for (int i = 0; i < 4; i++) p2[i] = __ldg(&src[tid + i * 256]);
        }
        #pragma unroll
        for (int kk = 0; kk < 32; kk++) {
            float4 h = *(const float4*)&Ht[(cb * 32 + kk) * XSTR + r0];
            float4 w = *(const float4*)&Ws[kk * E + c2];
            float hs[4] = {h.x, h.y, h.z, h.w};
            float wsv[4] = {w.x, w.y, w.z, w.w};
            #pragma unroll
            for (int i = 0; i < 4; i++)
                #pragma unroll
                for (int j = 0; j < 4; j++)
                    a2[i][j] = fmaf(hs[i], wsv[j], a2[i][j]);
        }
        __syncthreads();
    }

    // ---- bias2 + store ------------------------------------------------------
    {
        float4 bv = __ldg((const float4*)(b2 + k_ex * E + c2));
        #pragma unroll
        for (int i = 0; i < 4; i++) {
            int node = s_node[r0 + i];
            if (node >= 0) {
                float4 o;
                o.x = a2[i][0] + bv.x; o.y = a2[i][1] + bv.y;
                o.z = a2[i][2] + bv.z; o.w = a2[i][3] + bv.w;
                *(float4*)(outp + (size_t)node * E + c2) = o;
            }
        }
    }
}

// ---------------------------------------------------------------------------
// lf expert MLP: 256 -> relu(512) -> 128. Same structure; hidden in 2 passes.
// ---------------------------------------------------------------------------
__global__ void __launch_bounds__(256, 1)
lf_gemm_kernel(const float* __restrict__ W1, const float* __restrict__ b1,
               const float* __restrict__ W2, const float* __restrict__ b2) {
    extern __shared__ char smem[];
    float* Xt = (float*)(smem + LF_XT_OFF);       // [256][36]
    float* Ht = (float*)(smem + LF_HT_OFF);       // [512][36]
    float* Ws = (float*)(smem + LF_WS_OFF);
    int* s_node = (int*)(smem + LF_SN_OFF);

    int k_ex  = blockIdx.y;
    int count = g_counts[16 + k_ex];
    int m0    = blockIdx.x * TM;
    if (m0 >= count) return;
    int mrows = min(TM, count - m0);
    int tid   = threadIdx.x;

    if (tid < TM)
        s_node[tid] = (tid < mrows) ? g_lists[LBASE4 + k_ex * LFN + m0 + tid] : -1;
    __syncthreads();

    {   // stage X transposed
        int wid = tid >> 5, lane = tid & 31;
        #pragma unroll
        for (int i = 0; i < 4; i++) {
            int m = wid * 4 + i;
            int node = s_node[m];
            const float* src = 0;
            if (node >= 0) {
                int b = node / 9, g = node % 9;
                src = g_roots + ((size_t)b * Tt + 16 + 2 * g) * E;
            }
            #pragma unroll
            for (int j = 0; j < 8; j++) {
                int k = lane + 32 * j;
                Xt[k * XSTR + m] = src ? src[k] : 0.f;
            }
        }
    }

    int rg = tid & 7,  cg = tid >> 3;
    int r0 = rg * 4,   c0 = cg * 8;
    const float* W1k = W1 + (size_t)k_ex * TWO_E * 512;

    // ---- GEMM1 (hidden 512): two column-half passes ------------------------
    for (int pass = 0; pass < 2; pass++) {
        float acc[4][8];
        #pragma unroll
        for (int i = 0; i < 4; i++)
            #pragma unroll
            for (int j = 0; j < 8; j++) acc[i][j] = 0.f;

        float4 pre[8];
        {   // tile rows 0..31, cols [pass*256, +256): row is 128 float4 wide
            #pragma unroll
            for (int i = 0; i < 8; i++) {
                int f = tid + i * 256, r = f >> 6, c4 = f & 63;
                pre[i] = __ldg((const float4*)W1k + (size_t)r * 128 + pass * 64 + c4);
            }
        }
        for (int cb = 0; cb < 8; cb++) {
            float4* Wsv = (float4*)Ws;
            #pragma unroll
            for (int i = 0; i < 8; i++) Wsv[tid + i * 256] = pre[i];
            __syncthreads();
            if (cb < 7) {
                #pragma unroll
                for (int i = 0; i < 8; i++) {
                    int f = tid + i * 256, r = f >> 6, c4 = f & 63;
                    pre[i] = __ldg((const float4*)W1k
                                   + (size_t)((cb + 1) * 32 + r) * 128 + pass * 64 + c4);
                }
            }
            #pragma unroll
            for (int kk = 0; kk < 32; kk++) {
                float4 x  = *(const float4*)&Xt[(cb * 32 + kk) * XSTR + r0];
                float4 wa = *(const float4*)&Ws[kk * 256 + c0];
                float4 wb = *(const float4*)&Ws[kk * 256 + c0 + 4];
                float xs[4] = {x.x, x.y, x.z, x.w};
                float ws[8] = {wa.x, wa.y, wa.z, wa.w, wb.x, wb.y, wb.z, wb.w};
                #pragma unroll
                for (int i = 0; i < 4; i++)
                    #pragma unroll
                    for (int j = 0; j < 8; j++)
                        acc[i][j] = fmaf(xs[i], ws[j], acc[i][j]);
            }
            __syncthreads();
        }
        int cabs = pass * 256 + c0;
        float4 bva = __ldg((const float4*)(b1 + k_ex * 512 + cabs));
        float4 bvb = __ldg((const float4*)(b1 + k_ex * 512 + cabs + 4));
        float bv[8] = {bva.x, bva.y, bva.z, bva.w, bvb.x, bvb.y, bvb.z, bvb.w};
        #pragma unroll
        for (int j = 0; j < 8; j++) {
            float4 h;
            h.x = fmaxf(acc[0][j] + bv[j], 0.f);
            h.y = fmaxf(acc[1][j] + bv[j], 0.f);
            h.z = fmaxf(acc[2][j] + bv[j], 0.f);
            h.w = fmaxf(acc[3][j] + bv[j], 0.f);
            *(float4*)&Ht[(cabs + j) * XSTR + r0] = h;
        }
    }
    __syncthreads();

    // ---- GEMM2: K=512, 16 chunks of 32 -------------------------------------
    int c2 = (tid >> 3) * 4;
    float a2[4][4];
    #pragma unroll
    for (int i = 0; i < 4; i++)
        #pragma unroll
        for (int j = 0; j < 4; j++) a2[i][j] = 0.f;

    const float* W2k = W2 + (size_t)k_ex * 512 * E;
    float4 p2[4];
    {
        const float4* src = (const float4*)W2k;   // contiguous tile
        #pragma unroll
        for (int i = 0; i < 4; i++) p2[i] = __ldg(&src[tid + i * 256]);
    }
    for (int cb = 0; cb < 16; cb++) {
        float4* Wsv = (float4*)Ws;
        #pragma unroll
        for (int i = 0; i < 4; i++) Wsv[tid + i * 256] = p2[i];
        __syncthreads();
        if (cb < 15) {
            const float4* src = (const float4*)(W2k + (size_t)(cb + 1) * 32 * E);
            #pragma unroll
            for (int i = 0; i < 4; i++) p2[i] = __ldg(&src[tid + i * 256]);
        }
        #pragma unroll
        for (int kk = 0; kk < 32; kk++) {
            float4 h = *(const float4*)&Ht[(cb * 32 + kk) * XSTR + r0];
            float4 w = *(const float4*)&Ws[kk * E + c2];
            float hs[4] = {h.x, h.y, h.z, h.w};
            float wsv[4] = {w.x, w.y, w.z, w.w};
            #pragma unroll
            for (int i = 0; i < 4; i++)
                #pragma unroll
                for (int j = 0; j < 4; j++)
                    a2[i][j] = fmaf(hs[i], wsv[j], a2[i][j]);
        }
        __syncthreads();
    }
    {
        float4 bv = __ldg((const float4*)(b2 + k_ex * E + c2));
        #pragma unroll
        for (int i = 0; i < 4; i++) {
            int node = s_node[r0 + i];
            if (node >= 0) {
                float4 o;
                o.x = a2[i][0] + bv.x; o.y = a2[i][1] + bv.y;
                o.z = a2[i][2] + bv.z; o.w = a2[i][3] + bv.w;
                *(float4*)(g_stmt + (size_t)node * E + c2) = o;
            }
        }
    }
}

// ---------------------------------------------------------------------------
// Attention tail (unchanged; ~negligible time)
// ---------------------------------------------------------------------------
__global__ void attn_kernel(const int* __restrict__ th_idx,
                            const float* __restrict__ th_emb,
                            const float* __restrict__ he_W, const float* __restrict__ he_b,
                            const float* __restrict__ hg_W, const float* __restrict__ hg_b,
                            const float* __restrict__ ht_W, const float* __restrict__ ht_b,
                            float* __restrict__ out) {
    __shared__ float obj[E];
    __shared__ float q[E];
    __shared__ float keys[16][E + 1];
    __shared__ float a[16];
    int b = blockIdx.x, tid = threadIdx.x;

    float o = g_stmt[((size_t)b * 9 + 8) * E + tid];
    obj[tid] = o;
    out[(size_t)b * 512 + tid] = o;
    __syncthreads();

    for (int t3 = 0; t3 < 3; t3++) {
        int n; const float *W, *bb;
        if (t3 == 0) {
            n = 8; W = hg_W; bb = hg_b;
            for (int i = 0; i < 8; i++)
                keys[i][tid] = g_stmt[((size_t)b * 9 + i) * E + tid];
        } else if (t3 == 1) {
            n = 16; W = he_W; bb = he_b;
            for (int i = 0; i < 16; i++)
                keys[i][tid] = g_roots[((size_t)b * Tt + i) * E + tid];
        } else {
            n = 8; W = ht_W; bb = ht_b;
            for (int i = 0; i < 8; i++)
                keys[i][tid] = th_emb[(size_t)th_idx[b * 8 + i] * E + tid];
        }
        float qv = bb[tid];
        for (int k = 0; k < E; k++) qv = fmaf(obj[k], W[k * E + tid], qv);
        q[tid] = qv;
        __syncthreads();
        if (tid < n) {
            float s = 0.f;
            for (int d = 0; d < E; d++) s = fmaf(keys[tid][d], q[d], s);
            a[tid] = s;
        }
        __syncthreads();
        if (tid == 0) {
            float mx = -1e30f;
            for (int i = 0; i < n; i++) mx = fmaxf(mx, a[i]);
            float sum = 0.f;
            for (int i = 0; i < n; i++) { float e = expf(a[i] - mx); a[i] = e; sum += e; }
            float inv = 1.f / sum;
            for (int i = 0; i < n; i++) a[i] *= inv;
        }
        __syncthreads();
        float c = 0.f;
        for (int i = 0; i < n; i++) c = fmaf(a[i], keys[i][tid], c);
        int off = (t3 == 0) ? 128 : (t3 == 1) ? 256 : 384;
        out[(size_t)b * 512 + off + tid] = c;
        __syncthreads();
    }
}

// ---------------------------------------------------------------------------
extern "C" void kernel_launch(void* const* d_in, const int* in_sizes, int n_in,
                              void* d_out, int out_size) {
    const int*   leaf_idx = (const int*)d_in[0];
    const int*   nf_ids   = (const int*)d_in[1];
    const int*   lf_ids   = (const int*)d_in[2];
    const int*   th_idx   = (const int*)d_in[3];
    const float* ent_emb  = (const float*)d_in[4];
    const float* th_emb   = (const float*)d_in[5];
    const float* nf_W1 = (const float*)d_in[6];
    const float* nf_b1 = (const float*)d_in[7];
    const float* nf_W2 = (const float*)d_in[8];
    const float* nf_b2 = (const float*)d_in[9];
    const float* lf_W1 = (const float*)d_in[10];
    const float* lf_b1 = (const float*)d_in[11];
    const float* lf_W2 = (const float*)d_in[12];
    const float* lf_b2 = (const float*)d_in[13];
    const float* he_W = (const float*)d_in[14];
    const float* he_b = (const float*)d_in[15];
    const float* hg_W = (const float*)d_in[16];
    const float* hg_b = (const float*)d_in[17];
    const float* ht_W = (const float*)d_in[18];
    const float* ht_b = (const float*)d_in[19];
    float* out = (float*)d_out;

    cudaFuncSetAttribute(nf_gemm_kernel, cudaFuncAttributeMaxDynamicSharedMemorySize, NF_SMEM);
    cudaFuncSetAttribute(lf_gemm_kernel, cudaFuncAttributeMaxDynamicSharedMemorySize, LF_SMEM);

    zero_counts_kernel<<<1, 32>>>();
    compact_kernel<<<(L0N + L1N + L2N + L3N + LFN) / 256, 256>>>(nf_ids, lf_ids);

    nf_gemm_kernel<<<dim3(L0N / TM, 4), 256, NF_SMEM>>>(0, leaf_idx, ent_emb,
        nf_W1, nf_b1, nf_W2, nf_b2);
    nf_gemm_kernel<<<dim3(L1N / TM, 4), 256, NF_SMEM>>>(1, leaf_idx, ent_emb,
        nf_W1, nf_b1, nf_W2, nf_b2);
    nf_gemm_kernel<<<dim3(L2N / TM, 4), 256, NF_SMEM>>>(2, leaf_idx, ent_emb,
        nf_W1, nf_b1, nf_W2, nf_b2);
    nf_gemm_kernel<<<dim3(L3N / TM, 4), 256, NF_SMEM>>>(3, leaf_idx, ent_emb,
        nf_W1, nf_b1, nf_W2, nf_b2);

    lf_gemm_kernel<<<dim3(LFN / TM, 3), 256, LF_SMEM>>>(lf_W1, lf_b1, lf_W2, lf_b2);

    attn_kernel<<<Bn, E>>>(th_idx, th_emb, he_W, he_b, hg_W, hg_b, ht_W, ht_b, out);
}

// round 4
// speedup vs baseline: 4.4731x; 1.0380x over previous
#include <cuda_runtime.h>

// ---------------------------------------------------------------------------
// Problem constants
// ---------------------------------------------------------------------------
#define Bn      1024
#define Tt      34
#define E       128
#define TWO_E   256
#define L0N     (Bn*Tt*8)    // 278528
#define L1N     (Bn*Tt*4)    // 139264
#define L2N     (Bn*Tt*2)    // 69632
#define L3N     (Bn*Tt)      // 34816
#define LFN     (Bn*9)       // 9216
#define LBASE0  0
#define LBASE1  (LBASE0 + 4*L0N)
#define LBASE2  (LBASE1 + 4*L1N)
#define LBASE3  (LBASE2 + 4*L2N)
#define LBASE4  (LBASE3 + 4*L3N)
#define LTOTAL  (LBASE4 + 3*LFN)
#define TM      32
#define XSTR    36            // padded k-row stride for X_t / H_t (floats)

// smem layouts
#define NF_XT_OFF   0
#define NF_HT_OFF   36864
#define NF_WS_OFF   (36864 + 36864)
#define NF_SN_OFF   (NF_WS_OFF + 32768)
#define NF_SMEM     (NF_SN_OFF + 128)

#define LF_XT_OFF   0
#define LF_HT_OFF   36864
#define LF_WS_OFF   (36864 + 73728)
#define LF_SN_OFF   (LF_WS_OFF + 32768)
#define LF_SMEM     (LF_SN_OFF + 128)

typedef unsigned long long ull;

// ---------------------------------------------------------------------------
// Packed fp32x2 helpers (sm_103a). fma.rn.f32x2 is bit-exact: each half is an
// IEEE-754 fused fmaf. ptxas never emits it from C++; PTX-only path.
// ---------------------------------------------------------------------------
__device__ __forceinline__ void fma2(ull& d, ull a, ull b) {
    asm("fma.rn.f32x2 %0, %1, %2, %0;" : "+l"(d) : "l"(a), "l"(b));
}
__device__ __forceinline__ ull pack_dup(float w) {
    ull r; unsigned wi = __float_as_uint(w);
    asm("mov.b64 %0, {%1, %2};" : "=l"(r) : "r"(wi), "r"(wi));
    return r;
}
__device__ __forceinline__ float2 unpack2(ull v) {
    unsigned lo, hi;
    asm("mov.b64 {%0, %1}, %2;" : "=r"(lo), "=r"(hi) : "l"(v));
    float2 f; f.x = __uint_as_float(lo); f.y = __uint_as_float(hi);
    return f;
}

// ---------------------------------------------------------------------------
// Scratch (device globals; no allocation allowed)
// ---------------------------------------------------------------------------
__device__ float g_buf0[(size_t)L0N * E];
__device__ float g_buf1[(size_t)L1N * E];
__device__ float g_roots[(size_t)L3N * E];
__device__ float g_stmt[(size_t)LFN * E];
__device__ int   g_counts[20];
__device__ int   g_lists[LTOTAL];

__global__ void zero_counts_kernel() {
    if (threadIdx.x < 20) g_counts[threadIdx.x] = 0;
}

// ---------------------------------------------------------------------------
// Expert compaction (warp-aggregated atomics). Grid exact multiple of 256.
// ---------------------------------------------------------------------------
__global__ void compact_kernel(const int* __restrict__ nf_ids,
                               const int* __restrict__ lf_ids) {
    int gid = blockIdx.x * 256 + threadIdx.x;
    int slot, store_base, nid;
    if (gid < L0N) {
        nid = gid;
        int bt = nid >> 3, j = nid & 7;
        int id = nf_ids[bt * 15 + j];
        slot = id;               store_base = LBASE0 + id * L0N;
    } else if (gid < L0N + L1N) {
        nid = gid - L0N;
        int bt = nid >> 2, j = nid & 3;
        int id = nf_ids[bt * 15 + 8 + j];
        slot = 4 + id;           store_base = LBASE1 + id * L1N;
    } else if (gid < L0N + L1N + L2N) {
        nid = gid - (L0N + L1N);
        int bt = nid >> 1, j = nid & 1;
        int id = nf_ids[bt * 15 + 12 + j];
        slot = 8 + id;           store_base = LBASE2 + id * L2N;
    } else if (gid < L0N + L1N + L2N + L3N) {
        nid = gid - (L0N + L1N + L2N);
        int id = nf_ids[nid * 15 + 14];
        slot = 12 + id;          store_base = LBASE3 + id * L3N;
    } else {
        nid = gid - (L0N + L1N + L2N + L3N);
        int id = lf_ids[nid];
        slot = 16 + id;          store_base = LBASE4 + id * LFN;
    }
    unsigned mm = __match_any_sync(0xFFFFFFFFu, slot);
    int lane   = threadIdx.x & 31;
    int leader = __ffs(mm) - 1;
    int rank   = __popc(mm & ((1u << lane) - 1));
    int base   = 0;
    if (lane == leader) base = atomicAdd(&g_counts[slot], __popc(mm));
    base = __shfl_sync(0xFFFFFFFFu, base, leader);
    g_lists[store_base + base + rank] = nid;
}

// ---------------------------------------------------------------------------
// nf expert MLP: 256 -> relu(256) -> 128.  Register-blocked SGEMM with packed
// fp32x2 FMAs. Thread tile 4 rows x 8 cols; accumulators are 4x4 f32x2 pairs
// packed over columns (W pairs come straight from smem as ulonglong2; only
// the X scalar needs a 1-mov broadcast dup per row per k).
// ---------------------------------------------------------------------------
__global__ void __launch_bounds__(256, 2)
nf_gemm_kernel(int lvl,
               const int* __restrict__ leaf_idx,
               const float* __restrict__ ent_emb,
               const float* __restrict__ W1, const float* __restrict__ b1,
               const float* __restrict__ W2, const float* __restrict__ b2) {
    extern __shared__ char smem[];
    float* Xt = (float*)(smem + NF_XT_OFF);       // [256][36]
    float* Ht = (float*)(smem + NF_HT_OFF);       // [256][36]
    float* Ws = (float*)(smem + NF_WS_OFF);       // [32][256] / [32][128]
    int* s_node = (int*)(smem + NF_SN_OFF);

    int stride, list_base, counts_off;
    const float* in; float* outp;
    switch (lvl) {
        case 0:  stride = L0N; list_base = LBASE0; counts_off = 0;  in = 0;      outp = g_buf0;  break;
        case 1:  stride = L1N; list_base = LBASE1; counts_off = 4;  in = g_buf0; outp = g_buf1;  break;
        case 2:  stride = L2N; list_base = LBASE2; counts_off = 8;  in = g_buf1; outp = g_buf0;  break;
        default: stride = L3N; list_base = LBASE3; counts_off = 12; in = g_buf0; outp = g_roots; break;
    }

    int k_ex  = blockIdx.y;
    int count = g_counts[counts_off + k_ex];
    int m0    = blockIdx.x * TM;
    if (m0 >= count) return;
    int mrows = min(TM, count - m0);
    int tid   = threadIdx.x;

    if (tid < TM)
        s_node[tid] = (tid < mrows) ? g_lists[list_base + k_ex * stride + m0 + tid] : -1;
    __syncthreads();

    // ---- stage X transposed: X_t[k][m] -------------------------------------
    {
        int wid = tid >> 5, lane = tid & 31;
        #pragma unroll
        for (int i = 0; i < 4; i++) {
            int m = wid * 4 + i;
            int node = s_node[m];
            if (lvl == 0) {
                int l0 = 0, l1 = 0;
                if (node >= 0) { l0 = leaf_idx[node * 2]; l1 = leaf_idx[node * 2 + 1]; }
                #pragma unroll
                for (int j = 0; j < 8; j++) {
                    int k = lane + 32 * j;
                    float v = 0.f;
                    if (node >= 0)
                        v = (k < E) ? ent_emb[(size_t)l0 * E + k]
                                    : ent_emb[(size_t)l1 * E + (k - E)];
                    Xt[k * XSTR + m] = v;
                }
            } else {
                const float* src = (node >= 0) ? (in + (size_t)node * TWO_E) : 0;
                #pragma unroll
                for (int j = 0; j < 8; j++) {
                    int k = lane + 32 * j;
                    Xt[k * XSTR + m] = src ? src[k] : 0.f;
                }
            }
        }
    }

    // ---- GEMM1: 32x256 = X(32x256) @ W1(256x256), k-chunks of 32 ----------
    int rg = tid & 7,  cg = tid >> 3;
    int r0 = rg * 4,   c0 = cg * 8;
    const float* W1k = W1 + (size_t)k_ex * TWO_E * TWO_E;
    ull acc[4][4];                         // [row][colpair]
    #pragma unroll
    for (int i = 0; i < 4; i++)
        #pragma unroll
        for (int j = 0; j < 4; j++) acc[i][j] = 0ull;

    float4 pre[8];
    {
        const float4* src = (const float4*)W1k;
        #pragma unroll
        for (int i = 0; i < 8; i++) pre[i] = __ldg(&src[tid + i * 256]);
    }
    for (int cb = 0; cb < 8; cb++) {
        float4* Wsv = (float4*)Ws;
        #pragma unroll
        for (int i = 0; i < 8; i++) Wsv[tid + i * 256] = pre[i];
        __syncthreads();
        if (cb < 7) {
            const float4* src = (const float4*)(W1k + (cb + 1) * 32 * TWO_E);
            #pragma unroll
            for (int i = 0; i < 8; i++) pre[i] = __ldg(&src[tid + i * 256]);
        }
        #pragma unroll
        for (int kk = 0; kk < 32; kk++) {
            float4 x = *(const float4*)&Xt[(cb * 32 + kk) * XSTR + r0];
            ulonglong2 wa = *(const ulonglong2*)&Ws[kk * 256 + c0];
            ulonglong2 wb = *(const ulonglong2*)&Ws[kk * 256 + c0 + 4];
            ull xd[4] = {pack_dup(x.x), pack_dup(x.y), pack_dup(x.z), pack_dup(x.w)};
            #pragma unroll
            for (int i = 0; i < 4; i++) {
                fma2(acc[i][0], xd[i], wa.x);
                fma2(acc[i][1], xd[i], wa.y);
                fma2(acc[i][2], xd[i], wb.x);
                fma2(acc[i][3], xd[i], wb.y);
            }
        }
        __syncthreads();
    }

    // ---- bias + relu -> H_t[c][m] ------------------------------------------
    {
        float4 bva = __ldg((const float4*)(b1 + k_ex * TWO_E + c0));
        float4 bvb = __ldg((const float4*)(b1 + k_ex * TWO_E + c0 + 4));
        float bv[8] = {bva.x, bva.y, bva.z, bva.w, bvb.x, bvb.y, bvb.z, bvb.w};
        float a[4][8];
        #pragma unroll
        for (int i = 0; i < 4; i++)
            #pragma unroll
            for (int jp = 0; jp < 4; jp++) {
                float2 p = unpack2(acc[i][jp]);
                a[i][2 * jp]     = p.x;
                a[i][2 * jp + 1] = p.y;
            }
        #pragma unroll
        for (int j = 0; j < 8; j++) {
            float4 h;
            h.x = fmaxf(a[0][j] + bv[j], 0.f);
            h.y = fmaxf(a[1][j] + bv[j], 0.f);
            h.z = fmaxf(a[2][j] + bv[j], 0.f);
            h.w = fmaxf(a[3][j] + bv[j], 0.f);
            *(float4*)&Ht[(c0 + j) * XSTR + r0] = h;
        }
    }
    __syncthreads();

    // ---- GEMM2: 32x128 = H(32x256) @ W2(256x128), k-chunks of 32 -----------
    int c2 = (tid >> 3) * 4;
    ull a2[4][2];
    #pragma unroll
    for (int i = 0; i < 4; i++) { a2[i][0] = 0ull; a2[i][1] = 0ull; }

    const float* W2k = W2 + (size_t)k_ex * TWO_E * E;
    float4 p2[4];
    {
        const float4* src = (const float4*)W2k;
        #pragma unroll
        for (int i = 0; i < 4; i++) p2[i] = __ldg(&src[tid + i * 256]);
    }
    for (int cb = 0; cb < 8; cb++) {
        float4* Wsv = (float4*)Ws;
        #pragma unroll
        for (int i = 0; i < 4; i++) Wsv[tid + i * 256] = p2[i];
        __syncthreads();
        if (cb < 7) {
            const float4* src = (const float4*)(W2k + (cb + 1) * 32 * E);
            #pragma unroll
            for (int i = 0; i < 4; i++) p2[i] = __ldg(&src[tid + i * 256]);
        }
        #pragma unroll
        for (int kk = 0; kk < 32; kk++) {
            float4 h = *(const float4*)&Ht[(cb * 32 + kk) * XSTR + r0];
            ulonglong2 w = *(const ulonglong2*)&Ws[kk * E + c2];
            ull hd[4] = {pack_dup(h.x), pack_dup(h.y), pack_dup(h.z), pack_dup(h.w)};
            #pragma unroll
            for (int i = 0; i < 4; i++) {
                fma2(a2[i][0], hd[i], w.x);
                fma2(a2[i][1], hd[i], w.y);
            }
        }
        __syncthreads();
    }

    // ---- bias2 + store ------------------------------------------------------
    {
        float4 bv = __ldg((const float4*)(b2 + k_ex * E + c2));
        #pragma unroll
        for (int i = 0; i < 4; i++) {
            int node = s_node[r0 + i];
            if (node >= 0) {
                float2 pa = unpack2(a2[i][0]);
                float2 pb = unpack2(a2[i][1]);
                float4 o;
                o.x = pa.x + bv.x; o.y = pa.y + bv.y;
                o.z = pb.x + bv.z; o.w = pb.y + bv.w;
                *(float4*)(outp + (size_t)node * E + c2) = o;
            }
        }
    }
}

// ---------------------------------------------------------------------------
// lf expert MLP: 256 -> relu(512) -> 128. Same packed-f32x2 structure.
// ---------------------------------------------------------------------------
__global__ void __launch_bounds__(256, 1)
lf_gemm_kernel(const float* __restrict__ W1, const float* __restrict__ b1,
               const float* __restrict__ W2, const float* __restrict__ b2) {
    extern __shared__ char smem[];
    float* Xt = (float*)(smem + LF_XT_OFF);       // [256][36]
    float* Ht = (float*)(smem + LF_HT_OFF);       // [512][36]
    float* Ws = (float*)(smem + LF_WS_OFF);
    int* s_node = (int*)(smem + LF_SN_OFF);

    int k_ex  = blockIdx.y;
    int count = g_counts[16 + k_ex];
    int m0    = blockIdx.x * TM;
    if (m0 >= count) return;
    int mrows = min(TM, count - m0);
    int tid   = threadIdx.x;

    if (tid < TM)
        s_node[tid] = (tid < mrows) ? g_lists[LBASE4 + k_ex * LFN + m0 + tid] : -1;
    __syncthreads();

    {   // stage X transposed
        int wid = tid >> 5, lane = tid & 31;
        #pragma unroll
        for (int i = 0; i < 4; i++) {
            int m = wid * 4 + i;
            int node = s_node[m];
            const float* src = 0;
            if (node >= 0) {
                int b = node / 9, g = node % 9;
                src = g_roots + ((size_t)b * Tt + 16 + 2 * g) * E;
            }
            #pragma unroll
            for (int j = 0; j < 8; j++) {
                int k = lane + 32 * j;
                Xt[k * XSTR + m] = src ? src[k] : 0.f;
            }
        }
    }

    int rg = tid & 7,  cg = tid >> 3;
    int r0 = rg * 4,   c0 = cg * 8;
    const float* W1k = W1 + (size_t)k_ex * TWO_E * 512;

    // ---- GEMM1 (hidden 512): two column-half passes ------------------------
    for (int pass = 0; pass < 2; pass++) {
        ull acc[4][4];
        #pragma unroll
        for (int i = 0; i < 4; i++)
            #pragma unroll
            for (int j = 0; j < 4; j++) acc[i][j] = 0ull;

        float4 pre[8];
        {
            #pragma unroll
            for (int i = 0; i < 8; i++) {
                int f = tid + i * 256, r = f >> 6, c4 = f & 63;
                pre[i] = __ldg((const float4*)W1k + (size_t)r * 128 + pass * 64 + c4);
            }
        }
        for (int cb = 0; cb < 8; cb++) {
            float4* Wsv = (float4*)Ws;
            #pragma unroll
            for (int i = 0; i < 8; i++) Wsv[tid + i * 256] = pre[i];
            __syncthreads();
            if (cb < 7) {
                #pragma unroll
                for (int i = 0; i < 8; i++) {
                    int f = tid + i * 256, r = f >> 6, c4 = f & 63;
                    pre[i] = __ldg((const float4*)W1k
                                   + (size_t)((cb + 1) * 32 + r) * 128 + pass * 64 + c4);
                }
            }
            #pragma unroll
            for (int kk = 0; kk < 32; kk++) {
                float4 x = *(const float4*)&Xt[(cb * 32 + kk) * XSTR + r0];
                ulonglong2 wa = *(const ulonglong2*)&Ws[kk * 256 + c0];
                ulonglong2 wb = *(const ulonglong2*)&Ws[kk * 256 + c0 + 4];
                ull xd[4] = {pack_dup(x.x), pack_dup(x.y), pack_dup(x.z), pack_dup(x.w)};
                #pragma unroll
                for (int i = 0; i < 4; i++) {
                    fma2(acc[i][0], xd[i], wa.x);
                    fma2(acc[i][1], xd[i], wa.y);
                    fma2(acc[i][2], xd[i], wb.x);
                    fma2(acc[i][3], xd[i], wb.y);
                }
            }
            __syncthreads();
        }
        int cabs = pass * 256 + c0;
        float4 bva = __ldg((const float4*)(b1 + k_ex * 512 + cabs));
        float4 bvb = __ldg((const float4*)(b1 + k_ex * 512 + cabs + 4));
        float bv[8] = {bva.x, bva.y, bva.z, bva.w, bvb.x, bvb.y, bvb.z, bvb.w};
        float a[4][8];
        #pragma unroll
        for (int i = 0; i < 4; i++)
            #pragma unroll
            for (int jp = 0; jp < 4; jp++) {
                float2 p = unpack2(acc[i][jp]);
                a[i][2 * jp]     = p.x;
                a[i][2 * jp + 1] = p.y;
            }
        #pragma unroll
        for (int j = 0; j < 8; j++) {
            float4 h;
            h.x = fmaxf(a[0][j] + bv[j], 0.f);
            h.y = fmaxf(a[1][j] + bv[j], 0.f);
            h.z = fmaxf(a[2][j] + bv[j], 0.f);
            h.w = fmaxf(a[3][j] + bv[j], 0.f);
            *(float4*)&Ht[(cabs + j) * XSTR + r0] = h;
        }
    }
    __syncthreads();

    // ---- GEMM2: K=512, 16 chunks of 32 -------------------------------------
    int c2 = (tid >> 3) * 4;
    ull a2[4][2];
    #pragma unroll
    for (int i = 0; i < 4; i++) { a2[i][0] = 0ull; a2[i][1] = 0ull; }

    const float* W2k = W2 + (size_t)k_ex * 512 * E;
    float4 p2[4];
    {
        const float4* src = (const float4*)W2k;
        #pragma unroll
        for (int i = 0; i < 4; i++) p2[i] = __ldg(&src[tid + i * 256]);
    }
    for (int cb = 0; cb < 16; cb++) {
        float4* Wsv = (float4*)Ws;
        #pragma unroll
        for (int i = 0; i < 4; i++) Wsv[tid + i * 256] = p2[i];
        __syncthreads();
        if (cb < 15) {
            const float4* src = (const float4*)(W2k + (size_t)(cb + 1) * 32 * E);
            #pragma unroll
            for (int i = 0; i < 4; i++) p2[i] = __ldg(&src[tid + i * 256]);
        }
        #pragma unroll
        for (int kk = 0; kk < 32; kk++) {
            float4 h = *(const float4*)&Ht[(cb * 32 + kk) * XSTR + r0];
            ulonglong2 w = *(const ulonglong2*)&Ws[kk * E + c2];
            ull hd[4] = {pack_dup(h.x), pack_dup(h.y), pack_dup(h.z), pack_dup(h.w)};
            #pragma unroll
            for (int i = 0; i < 4; i++) {
                fma2(a2[i][0], hd[i], w.x);
                fma2(a2[i][1], hd[i], w.y);
            }
        }
        __syncthreads();
    }
    {
        float4 bv = __ldg((const float4*)(b2 + k_ex * E + c2));
        #pragma unroll
        for (int i = 0; i < 4; i++) {
            int node = s_node[r0 + i];
            if (node >= 0) {
                float2 pa = unpack2(a2[i][0]);
                float2 pb = unpack2(a2[i][1]);
                float4 o;
                o.x = pa.x + bv.x; o.y = pa.y + bv.y;
                o.z = pb.x + bv.z; o.w = pb.y + bv.w;
                *(float4*)(g_stmt + (size_t)node * E + c2) = o;
            }
        }
    }
}

// ---------------------------------------------------------------------------
// Attention tail (unchanged; ~negligible time)
// ---------------------------------------------------------------------------
__global__ void attn_kernel(const int* __restrict__ th_idx,
                            const float* __restrict__ th_emb,
                            const float* __restrict__ he_W, const float* __restrict__ he_b,
                            const float* __restrict__ hg_W, const float* __restrict__ hg_b,
                            const float* __restrict__ ht_W, const float* __restrict__ ht_b,
                            float* __restrict__ out) {
    __shared__ float obj[E];
    __shared__ float q[E];
    __shared__ float keys[16][E + 1];
    __shared__ float a[16];
    int b = blockIdx.x, tid = threadIdx.x;

    float o = g_stmt[((size_t)b * 9 + 8) * E + tid];
    obj[tid] = o;
    out[(size_t)b * 512 + tid] = o;
    __syncthreads();

    for (int t3 = 0; t3 < 3; t3++) {
        int n; const float *W, *bb;
        if (t3 == 0) {
            n = 8; W = hg_W; bb = hg_b;
            for (int i = 0; i < 8; i++)
                keys[i][tid] = g_stmt[((size_t)b * 9 + i) * E + tid];
        } else if (t3 == 1) {
            n = 16; W = he_W; bb = he_b;
            for (int i = 0; i < 16; i++)
                keys[i][tid] = g_roots[((size_t)b * Tt + i) * E + tid];
        } else {
            n = 8; W = ht_W; bb = ht_b;
            for (int i = 0; i < 8; i++)
                keys[i][tid] = th_emb[(size_t)th_idx[b * 8 + i] * E + tid];
        }
        float qv = bb[tid];
        for (int k = 0; k < E; k++) qv = fmaf(obj[k], W[k * E + tid], qv);
        q[tid] = qv;
        __syncthreads();
        if (tid < n) {
            float s = 0.f;
            for (int d = 0; d < E; d++) s = fmaf(keys[tid][d], q[d], s);
            a[tid] = s;
        }
        __syncthreads();
        if (tid == 0) {
            float mx = -1e30f;
            for (int i = 0; i < n; i++) mx = fmaxf(mx, a[i]);
            float sum = 0.f;
            for (int i = 0; i < n; i++) { float e = expf(a[i] - mx); a[i] = e; sum += e; }
            float inv = 1.f / sum;
            for (int i = 0; i < n; i++) a[i] *= inv;
        }
        __syncthreads();
        float c = 0.f;
        for (int i = 0; i < n; i++) c = fmaf(a[i], keys[i][tid], c);
        int off = (t3 == 0) ? 128 : (t3 == 1) ? 256 : 384;
        out[(size_t)b * 512 + off + tid] = c;
        __syncthreads();
    }
}

// ---------------------------------------------------------------------------
extern "C" void kernel_launch(void* const* d_in, const int* in_sizes, int n_in,
                              void* d_out, int out_size) {
    const int*   leaf_idx = (const int*)d_in[0];
    const int*   nf_ids   = (const int*)d_in[1];
    const int*   lf_ids   = (const int*)d_in[2];
    const int*   th_idx   = (const int*)d_in[3];
    const float* ent_emb  = (const float*)d_in[4];
    const float* th_emb   = (const float*)d_in[5];
    const float* nf_W1 = (const float*)d_in[6];
    const float* nf_b1 = (const float*)d_in[7];
    const float* nf_W2 = (const float*)d_in[8];
    const float* nf_b2 = (const float*)d_in[9];
    const float* lf_W1 = (const float*)d_in[10];
    const float* lf_b1 = (const float*)d_in[11];
    const float* lf_W2 = (const float*)d_in[12];
    const float* lf_b2 = (const float*)d_in[13];
    const float* he_W = (const float*)d_in[14];
    const float* he_b = (const float*)d_in[15];
    const float* hg_W = (const float*)d_in[16];
    const float* hg_b = (const float*)d_in[17];
    const float* ht_W = (const float*)d_in[18];
    const float* ht_b = (const float*)d_in[19];
    float* out = (float*)d_out;

    cudaFuncSetAttribute(nf_gemm_kernel, cudaFuncAttributeMaxDynamicSharedMemorySize, NF_SMEM);
    cudaFuncSetAttribute(lf_gemm_kernel, cudaFuncAttributeMaxDynamicSharedMemorySize, LF_SMEM);

    zero_counts_kernel<<<1, 32>>>();
    compact_kernel<<<(L0N + L1N + L2N + L3N + LFN) / 256, 256>>>(nf_ids, lf_ids);

    nf_gemm_kernel<<<dim3(L0N / TM, 4), 256, NF_SMEM>>>(0, leaf_idx, ent_emb,
        nf_W1, nf_b1, nf_W2, nf_b2);
    nf_gemm_kernel<<<dim3(L1N / TM, 4), 256, NF_SMEM>>>(1, leaf_idx, ent_emb,
        nf_W1, nf_b1, nf_W2, nf_b2);
    nf_gemm_kernel<<<dim3(L2N / TM, 4), 256, NF_SMEM>>>(2, leaf_idx, ent_emb,
        nf_W1, nf_b1, nf_W2, nf_b2);
    nf_gemm_kernel<<<dim3(L3N / TM, 4), 256, NF_SMEM>>>(3, leaf_idx, ent_emb,
        nf_W1, nf_b1, nf_W2, nf_b2);

    lf_gemm_kernel<<<dim3(LFN / TM, 3), 256, LF_SMEM>>>(lf_W1, lf_b1, lf_W2, lf_b2);

    attn_kernel<<<Bn, E>>>(th_idx, th_emb, he_W, he_b, hg_W, hg_b, ht_W, ht_b, out);
}